// round 1
// baseline (speedup 1.0000x reference)
#include <cuda_runtime.h>
#include <math.h>

// SelfAttentionEasy: b=2,h=16,s=2048,d=64, fp32.
// q: [b,h,s,d], k: [b,h,d,s] (pre-transposed), v: [b,h,s,d], out: [b,h,s,d]
// out = (exp(q@k/8) @ v) / rowsum(exp(q@k/8))
// No max subtraction needed: scores ~ N(0,1), exp stays tiny in fp32 range.

#define BM 64          // query rows per block
#define BN 64          // keys per tile
#define DD 64          // head dim
#define RS 68          // smem row stride (floats): 4*68 % 32 == 16 -> conflict-free
                       // column access; 68*4B = 272B, 16B-aligned rows for float4

__global__ __launch_bounds__(256, 2)
void attn_easy_kernel(const float* __restrict__ q,
                      const float* __restrict__ k,
                      const float* __restrict__ v,
                      float* __restrict__ out,
                      int S)
{
    extern __shared__ float sm[];
    float* Qs = sm;                 // [BM][RS]
    float* Ks = sm + BM * RS;       // [DD][RS] as K-tile, reused as P [BM][RS]
    float* Vs = sm + 2 * BM * RS;   // [BN][RS]

    const int bh = blockIdx.y;                 // 0..31
    const int q0 = blockIdx.x * BM;

    const int tid = threadIdx.x;
    const int tx = tid & 15;                   // 16 col-threads
    const int ty = tid >> 4;                   // 16 row-threads
    const int r0 = ty * 4;
    const int c0 = tx * 4;

    const float* qb = q + (size_t)bh * S * DD;
    const float* kb = k + (size_t)bh * DD * S;
    const float* vb = v + (size_t)bh * S * DD;
    float*       ob = out + (size_t)bh * S * DD;

    // Load Q tile once (coalesced)
    #pragma unroll
    for (int e = tid; e < BM * DD; e += 256) {
        int r = e >> 6, c = e & 63;
        Qs[r * RS + c] = qb[(q0 + r) * DD + c];
    }

    float acc[4][4];
    #pragma unroll
    for (int i = 0; i < 4; i++)
        #pragma unroll
        for (int j = 0; j < 4; j++) acc[i][j] = 0.f;
    float lsum[4] = {0.f, 0.f, 0.f, 0.f};

    for (int t0 = 0; t0 < S; t0 += BN) {
        __syncthreads();   // previous P fully consumed before refilling Ks

        // K tile: Ks[dd][tt] = kb[dd*S + t0+tt]  (coalesced along tt)
        #pragma unroll
        for (int e = tid; e < DD * BN; e += 256) {
            int dd = e >> 6, tt = e & 63;
            Ks[dd * RS + tt] = kb[dd * S + t0 + tt];
        }
        // V tile: Vs[tt][dd] = vb[(t0+tt)*DD + dd]  (coalesced along dd)
        #pragma unroll
        for (int e = tid; e < BN * DD; e += 256) {
            int tt = e >> 6, dd = e & 63;
            Vs[tt * RS + dd] = vb[(size_t)(t0 + tt) * DD + dd];
        }
        __syncthreads();

        // --- Phase A: S = Q @ K  (4x4 register tile per thread) ---
        float sreg[4][4];
        #pragma unroll
        for (int i = 0; i < 4; i++)
            #pragma unroll
            for (int j = 0; j < 4; j++) sreg[i][j] = 0.f;

        #pragma unroll 8
        for (int kk = 0; kk < DD; kk++) {
            float a[4];
            #pragma unroll
            for (int i = 0; i < 4; i++) a[i] = Qs[(r0 + i) * RS + kk];
            float4 bv = *reinterpret_cast<const float4*>(&Ks[kk * RS + c0]);
            float b[4] = {bv.x, bv.y, bv.z, bv.w};
            #pragma unroll
            for (int i = 0; i < 4; i++)
                #pragma unroll
                for (int j = 0; j < 4; j++)
                    sreg[i][j] = fmaf(a[i], b[j], sreg[i][j]);
        }
        __syncthreads();  // everyone done reading Ks -> reuse as P

        // --- Phase B: p = exp(s/8); partial row sums; P -> smem ---
        #pragma unroll
        for (int i = 0; i < 4; i++) {
            #pragma unroll
            for (int j = 0; j < 4; j++) {
                float p = __expf(sreg[i][j] * 0.125f);
                sreg[i][j] = p;
                lsum[i] += p;
            }
            float4 pv = make_float4(sreg[i][0], sreg[i][1], sreg[i][2], sreg[i][3]);
            *reinterpret_cast<float4*>(&Ks[(r0 + i) * RS + c0]) = pv;
        }
        __syncthreads();

        // --- Phase C: acc += P @ V ---
        #pragma unroll 8
        for (int kk = 0; kk < BN; kk++) {
            float a[4];
            #pragma unroll
            for (int i = 0; i < 4; i++) a[i] = Ks[(r0 + i) * RS + kk];
            float4 bv = *reinterpret_cast<const float4*>(&Vs[kk * RS + c0]);
            float b[4] = {bv.x, bv.y, bv.z, bv.w};
            #pragma unroll
            for (int i = 0; i < 4; i++)
                #pragma unroll
                for (int j = 0; j < 4; j++)
                    acc[i][j] = fmaf(a[i], b[j], acc[i][j]);
        }
    }

    // Reduce lsum across the 16 threads sharing the same rows (same ty).
    // lane = (ty&1)*16 + tx, so xor offsets 1,2,4,8 stay within the 16-group.
    #pragma unroll
    for (int i = 0; i < 4; i++) {
        float s = lsum[i];
        #pragma unroll
        for (int off = 8; off >= 1; off >>= 1)
            s += __shfl_xor_sync(0xffffffffu, s, off);
        lsum[i] = s;
    }

    // Write output: acc / l
    #pragma unroll
    for (int i = 0; i < 4; i++) {
        float inv = 1.0f / lsum[i];
        float4 o = make_float4(acc[i][0] * inv, acc[i][1] * inv,
                               acc[i][2] * inv, acc[i][3] * inv);
        *reinterpret_cast<float4*>(&ob[(size_t)(q0 + r0 + i) * DD + c0]) = o;
    }
}

extern "C" void kernel_launch(void* const* d_in, const int* in_sizes, int n_in,
                              void* d_out, int out_size)
{
    const float* q = (const float*)d_in[0];
    const float* k = (const float*)d_in[1];
    const float* v = (const float*)d_in[2];
    float* out = (float*)d_out;

    const int B = 2, H = 16, S = 2048;
    (void)in_sizes; (void)n_in; (void)out_size;

    size_t smem = (size_t)3 * BM * RS * sizeof(float);   // 52,224 B
    cudaFuncSetAttribute(attn_easy_kernel,
                         cudaFuncAttributeMaxDynamicSharedMemorySize, (int)smem);

    dim3 grid(S / BM, B * H);
    attn_easy_kernel<<<grid, 256, smem>>>(q, k, v, out, S);
}

// round 3
// speedup vs baseline: 4.2364x; 4.2364x over previous
#include <cuda_runtime.h>
#include <cuda_fp16.h>
#include <stdint.h>

// SelfAttentionEasy b=2,h=16,s=2048,d=64 fp32
// out = (exp(Q@K/8) @ V) / rowsum(exp(Q@K/8))
// HMMA mma.sync m16n8k16 fp16, 2-pass hi/lo split per GEMM (~2e-4 rel err).

#define S_LEN 2048
#define D     64
#define BM    128
#define BN    64

// smem byte offsets (dynamic smem is 1024-aligned)
#define SM_QH 0
#define SM_QL 16384
#define SM_K0 32768
#define SM_V0 40960
#define SM_K1 49152
#define SM_V1 57344
#define SM_TOTAL 65536

#define SWZ(o) ((uint32_t)(o) ^ ((((uint32_t)(o)) >> 3) & 0x70))

__device__ __forceinline__ uint32_t smem_u32(const void* p) {
    uint32_t a;
    asm("{ .reg .u64 t; cvta.to.shared.u64 t, %1; cvt.u32.u64 %0, t; }"
        : "=r"(a) : "l"(p));
    return a;
}
__device__ __forceinline__ uint32_t h2u(__half2 h) {
    return *reinterpret_cast<uint32_t*>(&h);
}

#define LDSM4(r, a) asm volatile(                                          \
    "ldmatrix.sync.aligned.m8n8.x4.shared.b16 {%0,%1,%2,%3}, [%4];"        \
    : "=r"((r)[0]),"=r"((r)[1]),"=r"((r)[2]),"=r"((r)[3]) : "r"(a))

#define LDSM4T(r, a) asm volatile(                                         \
    "ldmatrix.sync.aligned.m8n8.x4.trans.shared.b16 {%0,%1,%2,%3}, [%4];"  \
    : "=r"((r)[0]),"=r"((r)[1]),"=r"((r)[2]),"=r"((r)[3]) : "r"(a))

#define MMA(c, a, b0, b1) asm volatile(                                    \
    "mma.sync.aligned.m16n8k16.row.col.f32.f16.f16.f32 "                   \
    "{%0,%1,%2,%3},{%4,%5,%6,%7},{%8,%9},{%0,%1,%2,%3};"                   \
    : "+f"((c)[0]),"+f"((c)[1]),"+f"((c)[2]),"+f"((c)[3])                  \
    : "r"((a)[0]),"r"((a)[1]),"r"((a)[2]),"r"((a)[3]),"r"(b0),"r"(b1))

__global__ __launch_bounds__(256, 2)
void attn_hmma(const float* __restrict__ q, const float* __restrict__ k,
               const float* __restrict__ v, float* __restrict__ out)
{
    extern __shared__ char smem[];
    const uint32_t sb = smem_u32(smem);
    const int tid = threadIdx.x;
    const int wid = tid >> 5, lane = tid & 31;
    const int bh = blockIdx.y;
    const int q0 = blockIdx.x * BM;

    const float* qb = q + (size_t)bh * S_LEN * D + (size_t)q0 * D;
    const float* kb = k + (size_t)bh * D * S_LEN;
    const float* vb = v + (size_t)bh * S_LEN * D;
    float*       ob = out + (size_t)bh * S_LEN * D + (size_t)q0 * D;

    // ---- stage Q once: hi/lo fp16 split, [128 rows][64 d], 128B rows, SWZ ----
    #pragma unroll
    for (int i = 0; i < 8; i++) {
        int s = tid + i * 256;                 // 2048 float4 slots
        int row = s >> 4, c4 = s & 15;
        float4 f = *reinterpret_cast<const float4*>(qb + row * D + c4 * 4);
        __half2 h0 = __floats2half2_rn(f.x, f.y);
        __half2 h1 = __floats2half2_rn(f.z, f.w);
        float2 g0 = __half22float2(h0), g1 = __half22float2(h1);
        __half2 l0 = __floats2half2_rn(f.x - g0.x, f.y - g0.y);
        __half2 l1 = __floats2half2_rn(f.z - g1.x, f.w - g1.y);
        uint32_t off = SWZ(row * 128 + c4 * 8);
        *reinterpret_cast<uint2*>(smem + SM_QH + off) = make_uint2(h2u(h0), h2u(h1));
        *reinterpret_cast<uint2*>(smem + SM_QL + off) = make_uint2(h2u(l0), h2u(l1));
    }

    // ---- register-staged tile loader (K: [d][key], V: [key][d], fp16) ----
    uint32_t stg[16];
    {   // prologue: tile 0
        #pragma unroll
        for (int i = 0; i < 4; i++) {
            int s = tid + i * 256; int row = s >> 4, c4 = s & 15;
            float4 f = *reinterpret_cast<const float4*>(kb + (size_t)row * S_LEN + c4 * 4);
            stg[2*i]   = h2u(__floats2half2_rn(f.x, f.y));
            stg[2*i+1] = h2u(__floats2half2_rn(f.z, f.w));
        }
        #pragma unroll
        for (int i = 0; i < 4; i++) {
            int s = tid + i * 256; int row = s >> 4, c4 = s & 15;
            float4 f = *reinterpret_cast<const float4*>(vb + (size_t)row * D + c4 * 4);
            stg[8+2*i]   = h2u(__floats2half2_rn(f.x, f.y));
            stg[8+2*i+1] = h2u(__floats2half2_rn(f.z, f.w));
        }
        #pragma unroll
        for (int i = 0; i < 4; i++) {
            int s = tid + i * 256; int row = s >> 4, c4 = s & 15;
            uint32_t off = SWZ(row * 128 + c4 * 8);
            *reinterpret_cast<uint2*>(smem + SM_K0 + off) = make_uint2(stg[2*i], stg[2*i+1]);
            *reinterpret_cast<uint2*>(smem + SM_V0 + off) = make_uint2(stg[8+2*i], stg[8+2*i+1]);
        }
    }
    __syncthreads();

    float O[8][4];
    #pragma unroll
    for (int j = 0; j < 8; j++)
        #pragma unroll
        for (int e = 0; e < 4; e++) O[j][e] = 0.f;
    float lsum0 = 0.f, lsum1 = 0.f;

    const int wrow = wid * 16;
    const uint32_t arow = (uint32_t)(wrow + (lane & 15));  // A-frag ld row
    const uint32_t acb  = (uint32_t)(lane & 16);           // A-frag extra col bytes
    const uint32_t brow = (uint32_t)(lane & 15);           // B-frag row-in-block
    const uint32_t bcb  = (uint32_t)(lane & 16);

    for (int t = 0; t < 32; t++) {
        // prefetch next tile into regs (overlaps with MMA below)
        if (t < 31) {
            const int t0 = (t + 1) * BN;
            #pragma unroll
            for (int i = 0; i < 4; i++) {
                int s = tid + i * 256; int row = s >> 4, c4 = s & 15;
                float4 f = *reinterpret_cast<const float4*>(kb + (size_t)row * S_LEN + t0 + c4 * 4);
                stg[2*i]   = h2u(__floats2half2_rn(f.x, f.y));
                stg[2*i+1] = h2u(__floats2half2_rn(f.z, f.w));
            }
            #pragma unroll
            for (int i = 0; i < 4; i++) {
                int s = tid + i * 256; int row = s >> 4, c4 = s & 15;
                float4 f = *reinterpret_cast<const float4*>(vb + (size_t)(t0 + row) * D + c4 * 4);
                stg[8+2*i]   = h2u(__floats2half2_rn(f.x, f.y));
                stg[8+2*i+1] = h2u(__floats2half2_rn(f.z, f.w));
            }
        }

        const uint32_t Kb = sb + ((t & 1) ? SM_K1 : SM_K0);
        const uint32_t Vb = sb + ((t & 1) ? SM_V1 : SM_V0);

        // ---- S = Q @ K^T  (2-pass: Qh*K + Ql*K) ----
        float S[8][4];
        #pragma unroll
        for (int j = 0; j < 8; j++)
            #pragma unroll
            for (int e = 0; e < 4; e++) S[j][e] = 0.f;

        #pragma unroll
        for (int kk = 0; kk < 4; kk++) {
            uint32_t ah[4], al[4];
            LDSM4(ah, sb + SM_QH + SWZ(arow * 128 + 32 * kk + acb));
            LDSM4(al, sb + SM_QL + SWZ(arow * 128 + 32 * kk + acb));
            #pragma unroll
            for (int jp = 0; jp < 4; jp++) {
                uint32_t b[4];
                LDSM4T(b, Kb + SWZ((16 * kk + brow) * 128 + 32 * jp + bcb));
                MMA(S[2*jp],   ah, b[0], b[1]);
                MMA(S[2*jp+1], ah, b[2], b[3]);
                MMA(S[2*jp],   al, b[0], b[1]);
                MMA(S[2*jp+1], al, b[2], b[3]);
            }
        }

        // ---- p = exp(s/8); row sums; repack P into A-frags (hi/lo) ----
        uint32_t aph[4][4], apl[4][4];
        #pragma unroll
        for (int j = 0; j < 8; j++) {
            float p0 = __expf(S[j][0] * 0.125f);
            float p1 = __expf(S[j][1] * 0.125f);
            float p2 = __expf(S[j][2] * 0.125f);
            float p3 = __expf(S[j][3] * 0.125f);
            lsum0 += p0 + p1;
            lsum1 += p2 + p3;
            __half2 h01 = __floats2half2_rn(p0, p1);
            __half2 h23 = __floats2half2_rn(p2, p3);
            float2 f01 = __half22float2(h01), f23 = __half22float2(h23);
            __half2 l01 = __floats2half2_rn(p0 - f01.x, p1 - f01.y);
            __half2 l23 = __floats2half2_rn(p2 - f23.x, p3 - f23.y);
            int kk = j >> 1, pc = (j & 1) * 2;
            aph[kk][pc]   = h2u(h01);
            aph[kk][pc+1] = h2u(h23);
            apl[kk][pc]   = h2u(l01);
            apl[kk][pc+1] = h2u(l23);
        }

        // ---- O += P @ V  (2-pass: Ph*V + Pl*V) ----
        #pragma unroll
        for (int kk = 0; kk < 4; kk++) {
            #pragma unroll
            for (int jp = 0; jp < 4; jp++) {
                uint32_t b[4];
                LDSM4T(b, Vb + SWZ((16 * kk + brow) * 128 + 32 * jp + bcb));
                MMA(O[2*jp],   aph[kk], b[0], b[1]);
                MMA(O[2*jp+1], aph[kk], b[2], b[3]);
                MMA(O[2*jp],   apl[kk], b[0], b[1]);
                MMA(O[2*jp+1], apl[kk], b[2], b[3]);
            }
        }

        // store prefetched tile to the other buffer
        if (t < 31) {
            const uint32_t Kn = sb + ((t & 1) ? SM_K0 : SM_K1);
            const uint32_t Vn = sb + ((t & 1) ? SM_V0 : SM_V1);
            char* Knp = smem + (Kn - sb);
            char* Vnp = smem + (Vn - sb);
            #pragma unroll
            for (int i = 0; i < 4; i++) {
                int s = tid + i * 256; int row = s >> 4, c4 = s & 15;
                uint32_t off = SWZ(row * 128 + c4 * 8);
                *reinterpret_cast<uint2*>(Knp + off) = make_uint2(stg[2*i], stg[2*i+1]);
                *reinterpret_cast<uint2*>(Vnp + off) = make_uint2(stg[8+2*i], stg[8+2*i+1]);
            }
        }
        __syncthreads();
    }

    // ---- finalize: reduce row sums across lane quads, write O / l ----
    lsum0 += __shfl_xor_sync(0xffffffffu, lsum0, 1);
    lsum0 += __shfl_xor_sync(0xffffffffu, lsum0, 2);
    lsum1 += __shfl_xor_sync(0xffffffffu, lsum1, 1);
    lsum1 += __shfl_xor_sync(0xffffffffu, lsum1, 2);
    float inv0 = 1.0f / lsum0;
    float inv1 = 1.0f / lsum1;

    const int row = wrow + (lane >> 2);
    const int cb  = (lane & 3) * 2;
    #pragma unroll
    for (int j = 0; j < 8; j++) {
        float2 o0 = make_float2(O[j][0] * inv0, O[j][1] * inv0);
        float2 o1 = make_float2(O[j][2] * inv1, O[j][3] * inv1);
        *reinterpret_cast<float2*>(ob + (size_t)row * D + 8 * j + cb)       = o0;
        *reinterpret_cast<float2*>(ob + (size_t)(row + 8) * D + 8 * j + cb) = o1;
    }
}

extern "C" void kernel_launch(void* const* d_in, const int* in_sizes, int n_in,
                              void* d_out, int out_size)
{
    const float* q = (const float*)d_in[0];
    const float* k = (const float*)d_in[1];
    const float* v = (const float*)d_in[2];
    float* out = (float*)d_out;
    (void)in_sizes; (void)n_in; (void)out_size;

    cudaFuncSetAttribute(attn_hmma,
                         cudaFuncAttributeMaxDynamicSharedMemorySize, SM_TOTAL);
    dim3 grid(S_LEN / BM, 32);
    attn_hmma<<<grid, 256, SM_TOTAL>>>(q, k, v, out);
}

// round 4
// speedup vs baseline: 6.3815x; 1.5063x over previous
#include <cuda_runtime.h>
#include <cuda_fp16.h>
#include <stdint.h>

// SelfAttentionEasy b=2,h=16,s=2048,d=64 fp32
// out = (exp(Q@K/8) @ V) / rowsum(exp(Q@K/8))
// HMMA mma.sync m16n8k16 fp16, single pass per GEMM (~5e-4 rel err:
// P-weight rounding cancels under the final normalization).

#define S_LEN 2048
#define D     64
#define BM    128
#define BN    64

// smem byte offsets
#define SM_QH 0
#define SM_K0 16384
#define SM_V0 24576
#define SM_K1 32768
#define SM_V1 40960
#define SM_TOTAL 49152

#define SWZ(o) ((uint32_t)(o) ^ ((((uint32_t)(o)) >> 3) & 0x70))

__device__ __forceinline__ uint32_t smem_u32(const void* p) {
    uint32_t a;
    asm("{ .reg .u64 t; cvta.to.shared.u64 t, %1; cvt.u32.u64 %0, t; }"
        : "=r"(a) : "l"(p));
    return a;
}
__device__ __forceinline__ uint32_t h2u(__half2 h) {
    return *reinterpret_cast<uint32_t*>(&h);
}

#define LDSM4(r, a) asm volatile(                                          \
    "ldmatrix.sync.aligned.m8n8.x4.shared.b16 {%0,%1,%2,%3}, [%4];"        \
    : "=r"((r)[0]),"=r"((r)[1]),"=r"((r)[2]),"=r"((r)[3]) : "r"(a))

#define LDSM4T(r, a) asm volatile(                                         \
    "ldmatrix.sync.aligned.m8n8.x4.trans.shared.b16 {%0,%1,%2,%3}, [%4];"  \
    : "=r"((r)[0]),"=r"((r)[1]),"=r"((r)[2]),"=r"((r)[3]) : "r"(a))

#define MMA(c, a, b0, b1) asm volatile(                                    \
    "mma.sync.aligned.m16n8k16.row.col.f32.f16.f16.f32 "                   \
    "{%0,%1,%2,%3},{%4,%5,%6,%7},{%8,%9},{%0,%1,%2,%3};"                   \
    : "+f"((c)[0]),"+f"((c)[1]),"+f"((c)[2]),"+f"((c)[3])                  \
    : "r"((a)[0]),"r"((a)[1]),"r"((a)[2]),"r"((a)[3]),"r"(b0),"r"(b1))

__global__ __launch_bounds__(256, 2)
void attn_hmma(const float* __restrict__ q, const float* __restrict__ k,
               const float* __restrict__ v, float* __restrict__ out)
{
    extern __shared__ char smem[];
    const uint32_t sb = smem_u32(smem);
    const int tid = threadIdx.x;
    const int wid = tid >> 5, lane = tid & 31;
    const int bh = blockIdx.y;
    const int q0 = blockIdx.x * BM;

    const float* qb = q + (size_t)bh * S_LEN * D + (size_t)q0 * D;
    const float* kb = k + (size_t)bh * D * S_LEN;
    const float* vb = v + (size_t)bh * S_LEN * D;
    float*       ob = out + (size_t)bh * S_LEN * D + (size_t)q0 * D;

    // ---- stage Q once: fp16, [128 rows][64 d], 128B rows, SWZ ----
    #pragma unroll
    for (int i = 0; i < 8; i++) {
        int s = tid + i * 256;                 // 2048 float4 slots
        int row = s >> 4, c4 = s & 15;
        float4 f = *reinterpret_cast<const float4*>(qb + row * D + c4 * 4);
        __half2 h0 = __floats2half2_rn(f.x, f.y);
        __half2 h1 = __floats2half2_rn(f.z, f.w);
        uint32_t off = SWZ(row * 128 + c4 * 8);
        *reinterpret_cast<uint2*>(smem + SM_QH + off) = make_uint2(h2u(h0), h2u(h1));
    }

    // ---- register-staged tile loader (K: [d][key], V: [key][d], fp16) ----
    uint32_t stg[16];
    {   // prologue: tile 0
        #pragma unroll
        for (int i = 0; i < 4; i++) {
            int s = tid + i * 256; int row = s >> 4, c4 = s & 15;
            float4 f = *reinterpret_cast<const float4*>(kb + (size_t)row * S_LEN + c4 * 4);
            stg[2*i]   = h2u(__floats2half2_rn(f.x, f.y));
            stg[2*i+1] = h2u(__floats2half2_rn(f.z, f.w));
        }
        #pragma unroll
        for (int i = 0; i < 4; i++) {
            int s = tid + i * 256; int row = s >> 4, c4 = s & 15;
            float4 f = *reinterpret_cast<const float4*>(vb + (size_t)row * D + c4 * 4);
            stg[8+2*i]   = h2u(__floats2half2_rn(f.x, f.y));
            stg[8+2*i+1] = h2u(__floats2half2_rn(f.z, f.w));
        }
        #pragma unroll
        for (int i = 0; i < 4; i++) {
            int s = tid + i * 256; int row = s >> 4, c4 = s & 15;
            uint32_t off = SWZ(row * 128 + c4 * 8);
            *reinterpret_cast<uint2*>(smem + SM_K0 + off) = make_uint2(stg[2*i], stg[2*i+1]);
            *reinterpret_cast<uint2*>(smem + SM_V0 + off) = make_uint2(stg[8+2*i], stg[8+2*i+1]);
        }
    }
    __syncthreads();

    float O[8][4];
    #pragma unroll
    for (int j = 0; j < 8; j++)
        #pragma unroll
        for (int e = 0; e < 4; e++) O[j][e] = 0.f;
    float lsum0 = 0.f, lsum1 = 0.f;

    const int wrow = wid * 16;
    const uint32_t arow = (uint32_t)(wrow + (lane & 15));  // A-frag ld row
    const uint32_t acb  = (uint32_t)(lane & 16);           // A-frag extra col bytes
    const uint32_t brow = (uint32_t)(lane & 15);           // B-frag row-in-block
    const uint32_t bcb  = (uint32_t)(lane & 16);

    for (int t = 0; t < 32; t++) {
        // prefetch next tile into regs (overlaps with MMA below)
        if (t < 31) {
            const int t0 = (t + 1) * BN;
            #pragma unroll
            for (int i = 0; i < 4; i++) {
                int s = tid + i * 256; int row = s >> 4, c4 = s & 15;
                float4 f = *reinterpret_cast<const float4*>(kb + (size_t)row * S_LEN + t0 + c4 * 4);
                stg[2*i]   = h2u(__floats2half2_rn(f.x, f.y));
                stg[2*i+1] = h2u(__floats2half2_rn(f.z, f.w));
            }
            #pragma unroll
            for (int i = 0; i < 4; i++) {
                int s = tid + i * 256; int row = s >> 4, c4 = s & 15;
                float4 f = *reinterpret_cast<const float4*>(vb + (size_t)(t0 + row) * D + c4 * 4);
                stg[8+2*i]   = h2u(__floats2half2_rn(f.x, f.y));
                stg[8+2*i+1] = h2u(__floats2half2_rn(f.z, f.w));
            }
        }

        const uint32_t Kb = sb + ((t & 1) ? SM_K1 : SM_K0);
        const uint32_t Vb = sb + ((t & 1) ? SM_V1 : SM_V0);

        // ---- S = Q @ K^T  (single fp16 pass) ----
        float S[8][4];
        #pragma unroll
        for (int j = 0; j < 8; j++)
            #pragma unroll
            for (int e = 0; e < 4; e++) S[j][e] = 0.f;

        #pragma unroll
        for (int kk = 0; kk < 4; kk++) {
            uint32_t ah[4];
            LDSM4(ah, sb + SM_QH + SWZ(arow * 128 + 32 * kk + acb));
            #pragma unroll
            for (int jp = 0; jp < 4; jp++) {
                uint32_t b[4];
                LDSM4T(b, Kb + SWZ((16 * kk + brow) * 128 + 32 * jp + bcb));
                MMA(S[2*jp],   ah, b[0], b[1]);
                MMA(S[2*jp+1], ah, b[2], b[3]);
            }
        }

        // ---- p = exp(s/8); row sums; repack P into A-frags ----
        uint32_t aph[4][4];
        #pragma unroll
        for (int j = 0; j < 8; j++) {
            float p0 = __expf(S[j][0] * 0.125f);
            float p1 = __expf(S[j][1] * 0.125f);
            float p2 = __expf(S[j][2] * 0.125f);
            float p3 = __expf(S[j][3] * 0.125f);
            lsum0 += p0 + p1;
            lsum1 += p2 + p3;
            int kk = j >> 1, pc = (j & 1) * 2;
            aph[kk][pc]   = h2u(__floats2half2_rn(p0, p1));
            aph[kk][pc+1] = h2u(__floats2half2_rn(p2, p3));
        }

        // ---- O += P @ V  (single fp16 pass) ----
        #pragma unroll
        for (int kk = 0; kk < 4; kk++) {
            #pragma unroll
            for (int jp = 0; jp < 4; jp++) {
                uint32_t b[4];
                LDSM4T(b, Vb + SWZ((16 * kk + brow) * 128 + 32 * jp + bcb));
                MMA(O[2*jp],   aph[kk], b[0], b[1]);
                MMA(O[2*jp+1], aph[kk], b[2], b[3]);
            }
        }

        // store prefetched tile to the other buffer
        if (t < 31) {
            char* Knp = smem + ((t & 1) ? SM_K0 : SM_K1);
            char* Vnp = smem + ((t & 1) ? SM_V0 : SM_V1);
            #pragma unroll
            for (int i = 0; i < 4; i++) {
                int s = tid + i * 256; int row = s >> 4, c4 = s & 15;
                uint32_t off = SWZ(row * 128 + c4 * 8);
                *reinterpret_cast<uint2*>(Knp + off) = make_uint2(stg[2*i], stg[2*i+1]);
                *reinterpret_cast<uint2*>(Vnp + off) = make_uint2(stg[8+2*i], stg[8+2*i+1]);
            }
        }
        __syncthreads();
    }

    // ---- finalize: reduce row sums across lane quads, write O / l ----
    lsum0 += __shfl_xor_sync(0xffffffffu, lsum0, 1);
    lsum0 += __shfl_xor_sync(0xffffffffu, lsum0, 2);
    lsum1 += __shfl_xor_sync(0xffffffffu, lsum1, 1);
    lsum1 += __shfl_xor_sync(0xffffffffu, lsum1, 2);
    float inv0 = 1.0f / lsum0;
    float inv1 = 1.0f / lsum1;

    const int row = wrow + (lane >> 2);
    const int cb  = (lane & 3) * 2;
    #pragma unroll
    for (int j = 0; j < 8; j++) {
        float2 o0 = make_float2(O[j][0] * inv0, O[j][1] * inv0);
        float2 o1 = make_float2(O[j][2] * inv1, O[j][3] * inv1);
        *reinterpret_cast<float2*>(ob + (size_t)row * D + 8 * j + cb)       = o0;
        *reinterpret_cast<float2*>(ob + (size_t)(row + 8) * D + 8 * j + cb) = o1;
    }
}

extern "C" void kernel_launch(void* const* d_in, const int* in_sizes, int n_in,
                              void* d_out, int out_size)
{
    const float* q = (const float*)d_in[0];
    const float* k = (const float*)d_in[1];
    const float* v = (const float*)d_in[2];
    float* out = (float*)d_out;
    (void)in_sizes; (void)n_in; (void)out_size;

    cudaFuncSetAttribute(attn_hmma,
                         cudaFuncAttributeMaxDynamicSharedMemorySize, SM_TOTAL);
    dim3 grid(S_LEN / BM, 32);
    attn_hmma<<<grid, 256, SM_TOTAL>>>(q, k, v, out);
}

// round 5
// speedup vs baseline: 7.9700x; 1.2489x over previous
#include <cuda_runtime.h>
#include <cuda_fp16.h>
#include <stdint.h>

// SelfAttentionEasy b=2,h=16,s=2048,d=64 fp32
// out = (exp(Q@K/8) @ V) / rowsum(exp(Q@K/8))
// Round 5: fp16 pre-convert of K/V into device scratch, cp.async 3-stage
// pipeline, Q fragments resident in registers. Loop = LDSM + HMMA + exp only.

#define S_LEN 2048
#define D     64
#define BM    128
#define BN    64
#define NELEM (2*16*64*2048)          // elements per tensor (k or v)

__device__ __half g_kh[NELEM];        // k as fp16, layout [bh][d][s]
__device__ __half g_vh[NELEM];        // v as fp16, layout [bh][s][d]

#define SM_TOTAL 49152                // 3 stages x (8KB K + 8KB V)

#define SWZ(o) ((uint32_t)(o) ^ ((((uint32_t)(o)) >> 3) & 0x70))

__device__ __forceinline__ uint32_t smem_u32(const void* p) {
    uint32_t a;
    asm("{ .reg .u64 t; cvta.to.shared.u64 t, %1; cvt.u32.u64 %0, t; }"
        : "=r"(a) : "l"(p));
    return a;
}
__device__ __forceinline__ uint32_t h2u(__half2 h) {
    return *reinterpret_cast<uint32_t*>(&h);
}

#define LDSM4(r, a) asm volatile(                                          \
    "ldmatrix.sync.aligned.m8n8.x4.shared.b16 {%0,%1,%2,%3}, [%4];"        \
    : "=r"((r)[0]),"=r"((r)[1]),"=r"((r)[2]),"=r"((r)[3]) : "r"(a))

#define LDSM4T(r, a) asm volatile(                                         \
    "ldmatrix.sync.aligned.m8n8.x4.trans.shared.b16 {%0,%1,%2,%3}, [%4];"  \
    : "=r"((r)[0]),"=r"((r)[1]),"=r"((r)[2]),"=r"((r)[3]) : "r"(a))

#define MMA(c, a, b0, b1) asm volatile(                                    \
    "mma.sync.aligned.m16n8k16.row.col.f32.f16.f16.f32 "                   \
    "{%0,%1,%2,%3},{%4,%5,%6,%7},{%8,%9},{%0,%1,%2,%3};"                   \
    : "+f"((c)[0]),"+f"((c)[1]),"+f"((c)[2]),"+f"((c)[3])                  \
    : "r"((a)[0]),"r"((a)[1]),"r"((a)[2]),"r"((a)[3]),"r"(b0),"r"(b1))

#define CPA(dst, src) asm volatile(                                        \
    "cp.async.cg.shared.global [%0], [%1], 16;" :: "r"(dst), "l"(src))
#define CPA_COMMIT() asm volatile("cp.async.commit_group;" ::: "memory")
#define CPA_WAIT1()  asm volatile("cp.async.wait_group 1;" ::: "memory")
#define CPA_WAIT0()  asm volatile("cp.async.wait_group 0;" ::: "memory")

// ---- prepass: fp32 -> fp16 bulk convert ----
__global__ void cvt_k(const float* __restrict__ src) {
    size_t i = ((size_t)blockIdx.x * blockDim.x + threadIdx.x) * 8;
    float4 a = *reinterpret_cast<const float4*>(src + i);
    float4 b = *reinterpret_cast<const float4*>(src + i + 4);
    uint4 o;
    o.x = h2u(__floats2half2_rn(a.x, a.y));
    o.y = h2u(__floats2half2_rn(a.z, a.w));
    o.z = h2u(__floats2half2_rn(b.x, b.y));
    o.w = h2u(__floats2half2_rn(b.z, b.w));
    *reinterpret_cast<uint4*>(g_kh + i) = o;
}
__global__ void cvt_v(const float* __restrict__ src) {
    size_t i = ((size_t)blockIdx.x * blockDim.x + threadIdx.x) * 8;
    float4 a = *reinterpret_cast<const float4*>(src + i);
    float4 b = *reinterpret_cast<const float4*>(src + i + 4);
    uint4 o;
    o.x = h2u(__floats2half2_rn(a.x, a.y));
    o.y = h2u(__floats2half2_rn(a.z, a.w));
    o.z = h2u(__floats2half2_rn(b.x, b.y));
    o.w = h2u(__floats2half2_rn(b.z, b.w));
    *reinterpret_cast<uint4*>(g_vh + i) = o;
}

__global__ __launch_bounds__(256, 2)
void attn_hmma(const float* __restrict__ q, float* __restrict__ out)
{
    extern __shared__ char smem[];
    const uint32_t sb = smem_u32(smem);
    const int tid = threadIdx.x;
    const int wid = tid >> 5, lane = tid & 31;
    const int bh = blockIdx.y;
    const int q0 = blockIdx.x * BM;

    const float*  qb  = q + (size_t)bh * S_LEN * D + (size_t)q0 * D;
    const __half* khb = g_kh + (size_t)bh * D * S_LEN;
    const __half* vhb = g_vh + (size_t)bh * S_LEN * D;
    float*        ob  = out + (size_t)bh * S_LEN * D + (size_t)q0 * D;

    const int wrow = wid * 16;
    const uint32_t arow = (uint32_t)(wrow + (lane & 15));
    const uint32_t acb  = (uint32_t)(lane & 16);
    const uint32_t brow = (uint32_t)(lane & 15);
    const uint32_t bcb  = (uint32_t)(lane & 16);

    // ---- stage Q once through smem (stage-0 region, 16KB), hoist to regs ----
    #pragma unroll
    for (int i = 0; i < 8; i++) {
        int s = tid + i * 256;                 // 2048 float4 slots
        int row = s >> 4, c4 = s & 15;
        float4 f = *reinterpret_cast<const float4*>(qb + row * D + c4 * 4);
        uint32_t off = SWZ(row * 128 + c4 * 8);
        *reinterpret_cast<uint2*>(smem + off) =
            make_uint2(h2u(__floats2half2_rn(f.x, f.y)),
                       h2u(__floats2half2_rn(f.z, f.w)));
    }
    __syncthreads();
    uint32_t aq[4][4];
    #pragma unroll
    for (int kk = 0; kk < 4; kk++)
        LDSM4(aq[kk], sb + SWZ(arow * 128 + 32 * kk + acb));
    __syncthreads();   // Q frags read; stage-0 smem reusable

    // per-thread cp.async source rows/chunks
    const int e0 = tid, e1 = tid + 256;
    const int r0_ = e0 >> 3, c0_ = e0 & 7;
    const int r1_ = e1 >> 3, c1_ = e1 & 7;

    // ---- cp.async prologue: stages for tiles 0 and 1 ----
    #pragma unroll
    for (int p = 0; p < 2; p++) {
        uint32_t kd = sb + p * 16384;
        uint32_t vd = kd + 8192;
        const int t0 = p * BN;
        CPA(kd + SWZ(r0_ * 128 + c0_ * 16), khb + (size_t)r0_ * S_LEN + t0 + c0_ * 8);
        CPA(kd + SWZ(r1_ * 128 + c1_ * 16), khb + (size_t)r1_ * S_LEN + t0 + c1_ * 8);
        CPA(vd + SWZ(r0_ * 128 + c0_ * 16), vhb + (size_t)(t0 + r0_) * D + c0_ * 8);
        CPA(vd + SWZ(r1_ * 128 + c1_ * 16), vhb + (size_t)(t0 + r1_) * D + c1_ * 8);
        CPA_COMMIT();
    }

    float O[8][4];
    #pragma unroll
    for (int j = 0; j < 8; j++)
        #pragma unroll
        for (int e = 0; e < 4; e++) O[j][e] = 0.f;
    float lsum0 = 0.f, lsum1 = 0.f;

    int scur = 0, snxt = 2;   // stage of tile t, stage to fill with tile t+2

    for (int t = 0; t < 32; t++) {
        if (t < 31) { CPA_WAIT1(); } else { CPA_WAIT0(); }
        __syncthreads();   // stage t visible to all; all warps done with t-1

        // issue tile t+2 into stage snxt (overlaps with MMA below)
        if (t + 2 < 32) {
            uint32_t kd = sb + snxt * 16384;
            uint32_t vd = kd + 8192;
            const int t0 = (t + 2) * BN;
            CPA(kd + SWZ(r0_ * 128 + c0_ * 16), khb + (size_t)r0_ * S_LEN + t0 + c0_ * 8);
            CPA(kd + SWZ(r1_ * 128 + c1_ * 16), khb + (size_t)r1_ * S_LEN + t0 + c1_ * 8);
            CPA(vd + SWZ(r0_ * 128 + c0_ * 16), vhb + (size_t)(t0 + r0_) * D + c0_ * 8);
            CPA(vd + SWZ(r1_ * 128 + c1_ * 16), vhb + (size_t)(t0 + r1_) * D + c1_ * 8);
            CPA_COMMIT();
        }

        const uint32_t Kb = sb + scur * 16384;
        const uint32_t Vb = Kb + 8192;

        // ---- S = Q @ K^T ----
        float S[8][4];
        #pragma unroll
        for (int j = 0; j < 8; j++)
            #pragma unroll
            for (int e = 0; e < 4; e++) S[j][e] = 0.f;

        #pragma unroll
        for (int kk = 0; kk < 4; kk++) {
            #pragma unroll
            for (int jp = 0; jp < 4; jp++) {
                uint32_t b[4];
                LDSM4T(b, Kb + SWZ((16 * kk + brow) * 128 + 32 * jp + bcb));
                MMA(S[2*jp],   aq[kk], b[0], b[1]);
                MMA(S[2*jp+1], aq[kk], b[2], b[3]);
            }
        }

        // ---- p = exp(s/8); row sums; repack P into A-frags ----
        uint32_t aph[4][4];
        #pragma unroll
        for (int j = 0; j < 8; j++) {
            float p0 = __expf(S[j][0] * 0.125f);
            float p1 = __expf(S[j][1] * 0.125f);
            float p2 = __expf(S[j][2] * 0.125f);
            float p3 = __expf(S[j][3] * 0.125f);
            lsum0 += p0 + p1;
            lsum1 += p2 + p3;
            int kk = j >> 1, pc = (j & 1) * 2;
            aph[kk][pc]   = h2u(__floats2half2_rn(p0, p1));
            aph[kk][pc+1] = h2u(__floats2half2_rn(p2, p3));
        }

        // ---- O += P @ V ----
        #pragma unroll
        for (int kk = 0; kk < 4; kk++) {
            #pragma unroll
            for (int jp = 0; jp < 4; jp++) {
                uint32_t b[4];
                LDSM4T(b, Vb + SWZ((16 * kk + brow) * 128 + 32 * jp + bcb));
                MMA(O[2*jp],   aph[kk], b[0], b[1]);
                MMA(O[2*jp+1], aph[kk], b[2], b[3]);
            }
        }

        scur = (scur == 2) ? 0 : scur + 1;
        snxt = (snxt == 2) ? 0 : snxt + 1;
    }

    // ---- finalize: reduce row sums across lane quads, write O / l ----
    lsum0 += __shfl_xor_sync(0xffffffffu, lsum0, 1);
    lsum0 += __shfl_xor_sync(0xffffffffu, lsum0, 2);
    lsum1 += __shfl_xor_sync(0xffffffffu, lsum1, 1);
    lsum1 += __shfl_xor_sync(0xffffffffu, lsum1, 2);
    float inv0 = 1.0f / lsum0;
    float inv1 = 1.0f / lsum1;

    const int row = wrow + (lane >> 2);
    const int cb  = (lane & 3) * 2;
    #pragma unroll
    for (int j = 0; j < 8; j++) {
        float2 o0 = make_float2(O[j][0] * inv0, O[j][1] * inv0);
        float2 o1 = make_float2(O[j][2] * inv1, O[j][3] * inv1);
        *reinterpret_cast<float2*>(ob + (size_t)row * D + 8 * j + cb)       = o0;
        *reinterpret_cast<float2*>(ob + (size_t)(row + 8) * D + 8 * j + cb) = o1;
    }
}

extern "C" void kernel_launch(void* const* d_in, const int* in_sizes, int n_in,
                              void* d_out, int out_size)
{
    const float* q = (const float*)d_in[0];
    const float* k = (const float*)d_in[1];
    const float* v = (const float*)d_in[2];
    float* out = (float*)d_out;
    (void)in_sizes; (void)n_in; (void)out_size;

    // prepass: fp32 -> fp16 for K and V (NELEM/8 threads each)
    cvt_k<<<NELEM / 8 / 256, 256>>>(k);
    cvt_v<<<NELEM / 8 / 256, 256>>>(v);

    cudaFuncSetAttribute(attn_hmma,
                         cudaFuncAttributeMaxDynamicSharedMemorySize, SM_TOTAL);
    dim3 grid(S_LEN / BM, 32);
    attn_hmma<<<grid, 256, SM_TOTAL>>>(q, out);
}

// round 6
// speedup vs baseline: 8.7766x; 1.1012x over previous
#include <cuda_runtime.h>
#include <cuda_fp16.h>
#include <stdint.h>

// SelfAttentionEasy b=2,h=16,s=2048,d=64 fp32
// out = (exp(Q@K/8) @ V) / rowsum(exp(Q@K/8))
// Round 6: Q pre-scaled by log2(e)/8 so S = log2(p); p = ex2.approx.f16x2(S).
// Row sums computed as P @ ones on the tensor pipe. Fused fp16 prepass.

#define S_LEN 2048
#define D     64
#define BM    128
#define BN    64
#define NELEM (2*16*64*2048)          // elements per tensor (k or v)
#define QSCALE 0.18033688011112042f   // log2(e)/8

__device__ __half g_kh[NELEM];        // k as fp16, layout [bh][d][s]
__device__ __half g_vh[NELEM];        // v as fp16, layout [bh][s][d]

#define SM_TOTAL 49152                // 3 stages x (8KB K + 8KB V)

#define SWZ(o) ((uint32_t)(o) ^ ((((uint32_t)(o)) >> 3) & 0x70))

__device__ __forceinline__ uint32_t smem_u32(const void* p) {
    uint32_t a;
    asm("{ .reg .u64 t; cvta.to.shared.u64 t, %1; cvt.u32.u64 %0, t; }"
        : "=r"(a) : "l"(p));
    return a;
}
__device__ __forceinline__ uint32_t h2u(__half2 h) {
    return *reinterpret_cast<uint32_t*>(&h);
}

#define LDSM4(r, a) asm volatile(                                          \
    "ldmatrix.sync.aligned.m8n8.x4.shared.b16 {%0,%1,%2,%3}, [%4];"        \
    : "=r"((r)[0]),"=r"((r)[1]),"=r"((r)[2]),"=r"((r)[3]) : "r"(a))

#define LDSM4T(r, a) asm volatile(                                         \
    "ldmatrix.sync.aligned.m8n8.x4.trans.shared.b16 {%0,%1,%2,%3}, [%4];"  \
    : "=r"((r)[0]),"=r"((r)[1]),"=r"((r)[2]),"=r"((r)[3]) : "r"(a))

#define MMA(c, a, b0, b1) asm volatile(                                    \
    "mma.sync.aligned.m16n8k16.row.col.f32.f16.f16.f32 "                   \
    "{%0,%1,%2,%3},{%4,%5,%6,%7},{%8,%9},{%0,%1,%2,%3};"                   \
    : "+f"((c)[0]),"+f"((c)[1]),"+f"((c)[2]),"+f"((c)[3])                  \
    : "r"((a)[0]),"r"((a)[1]),"r"((a)[2]),"r"((a)[3]),"r"(b0),"r"(b1))

#define CPA(dst, src) asm volatile(                                        \
    "cp.async.cg.shared.global [%0], [%1], 16;" :: "r"(dst), "l"(src))
#define CPA_COMMIT() asm volatile("cp.async.commit_group;" ::: "memory")
#define CPA_WAIT1()  asm volatile("cp.async.wait_group 1;" ::: "memory")
#define CPA_WAIT0()  asm volatile("cp.async.wait_group 0;" ::: "memory")

// ---- fused prepass: fp32 -> fp16 bulk convert for K and V ----
__global__ void cvt_kv(const float* __restrict__ k, const float* __restrict__ v) {
    size_t gi = (size_t)blockIdx.x * blockDim.x + threadIdx.x;
    const size_t half = (size_t)NELEM / 8;     // float4-pairs per tensor
    const float* src;
    __half* dst;
    size_t i;
    if (gi < half) { src = k; dst = g_kh; i = gi * 8; }
    else           { src = v; dst = g_vh; i = (gi - half) * 8; }
    float4 a = *reinterpret_cast<const float4*>(src + i);
    float4 b = *reinterpret_cast<const float4*>(src + i + 4);
    uint4 o;
    o.x = h2u(__floats2half2_rn(a.x, a.y));
    o.y = h2u(__floats2half2_rn(a.z, a.w));
    o.z = h2u(__floats2half2_rn(b.x, b.y));
    o.w = h2u(__floats2half2_rn(b.z, b.w));
    *reinterpret_cast<uint4*>(dst + i) = o;
}

__global__ __launch_bounds__(256, 2)
void attn_hmma(const float* __restrict__ q, float* __restrict__ out)
{
    extern __shared__ char smem[];
    const uint32_t sb = smem_u32(smem);
    const int tid = threadIdx.x;
    const int wid = tid >> 5, lane = tid & 31;
    const int bh = blockIdx.y;
    const int q0 = blockIdx.x * BM;

    const float*  qb  = q + (size_t)bh * S_LEN * D + (size_t)q0 * D;
    const __half* khb = g_kh + (size_t)bh * D * S_LEN;
    const __half* vhb = g_vh + (size_t)bh * S_LEN * D;
    float*        ob  = out + (size_t)bh * S_LEN * D + (size_t)q0 * D;

    const int wrow = wid * 16;
    const uint32_t arow = (uint32_t)(wrow + (lane & 15));
    const uint32_t acb  = (uint32_t)(lane & 16);
    const uint32_t brow = (uint32_t)(lane & 15);
    const uint32_t bcb  = (uint32_t)(lane & 16);

    // ---- stage Q once (pre-scaled by log2e/8), hoist frags to regs ----
    #pragma unroll
    for (int i = 0; i < 8; i++) {
        int s = tid + i * 256;                 // 2048 float4 slots
        int row = s >> 4, c4 = s & 15;
        float4 f = *reinterpret_cast<const float4*>(qb + row * D + c4 * 4);
        uint32_t off = SWZ(row * 128 + c4 * 8);
        *reinterpret_cast<uint2*>(smem + off) =
            make_uint2(h2u(__floats2half2_rn(f.x * QSCALE, f.y * QSCALE)),
                       h2u(__floats2half2_rn(f.z * QSCALE, f.w * QSCALE)));
    }
    __syncthreads();
    uint32_t aq[4][4];
    #pragma unroll
    for (int kk = 0; kk < 4; kk++)
        LDSM4(aq[kk], sb + SWZ(arow * 128 + 32 * kk + acb));
    __syncthreads();   // Q frags read; stage-0 smem reusable

    // per-thread cp.async source rows/chunks
    const int e0 = tid, e1 = tid + 256;
    const int r0_ = e0 >> 3, c0_ = e0 & 7;
    const int r1_ = e1 >> 3, c1_ = e1 & 7;

    // ---- cp.async prologue: stages for tiles 0 and 1 ----
    #pragma unroll
    for (int p = 0; p < 2; p++) {
        uint32_t kd = sb + p * 16384;
        uint32_t vd = kd + 8192;
        const int t0 = p * BN;
        CPA(kd + SWZ(r0_ * 128 + c0_ * 16), khb + (size_t)r0_ * S_LEN + t0 + c0_ * 8);
        CPA(kd + SWZ(r1_ * 128 + c1_ * 16), khb + (size_t)r1_ * S_LEN + t0 + c1_ * 8);
        CPA(vd + SWZ(r0_ * 128 + c0_ * 16), vhb + (size_t)(t0 + r0_) * D + c0_ * 8);
        CPA(vd + SWZ(r1_ * 128 + c1_ * 16), vhb + (size_t)(t0 + r1_) * D + c1_ * 8);
        CPA_COMMIT();
    }

    float O[8][4];
    #pragma unroll
    for (int j = 0; j < 8; j++)
        #pragma unroll
        for (int e = 0; e < 4; e++) O[j][e] = 0.f;
    float L[4] = {0.f, 0.f, 0.f, 0.f};         // rowsum accumulator (P @ ones)
    const uint32_t ONES = 0x3C003C00u;          // half2(1,1)

    int scur = 0, snxt = 2;

    for (int t = 0; t < 32; t++) {
        if (t < 31) { CPA_WAIT1(); } else { CPA_WAIT0(); }
        __syncthreads();

        // issue tile t+2 into stage snxt
        if (t + 2 < 32) {
            uint32_t kd = sb + snxt * 16384;
            uint32_t vd = kd + 8192;
            const int t0 = (t + 2) * BN;
            CPA(kd + SWZ(r0_ * 128 + c0_ * 16), khb + (size_t)r0_ * S_LEN + t0 + c0_ * 8);
            CPA(kd + SWZ(r1_ * 128 + c1_ * 16), khb + (size_t)r1_ * S_LEN + t0 + c1_ * 8);
            CPA(vd + SWZ(r0_ * 128 + c0_ * 16), vhb + (size_t)(t0 + r0_) * D + c0_ * 8);
            CPA(vd + SWZ(r1_ * 128 + c1_ * 16), vhb + (size_t)(t0 + r1_) * D + c1_ * 8);
            CPA_COMMIT();
        }

        const uint32_t Kb = sb + scur * 16384;
        const uint32_t Vb = Kb + 8192;

        // ---- S = (Q*log2e/8) @ K^T  => S = log2(p) ----
        float S[8][4];
        #pragma unroll
        for (int j = 0; j < 8; j++)
            #pragma unroll
            for (int e = 0; e < 4; e++) S[j][e] = 0.f;

        #pragma unroll
        for (int kk = 0; kk < 4; kk++) {
            #pragma unroll
            for (int jp = 0; jp < 4; jp++) {
                uint32_t b[4];
                LDSM4T(b, Kb + SWZ((16 * kk + brow) * 128 + 32 * jp + bcb));
                MMA(S[2*jp],   aq[kk], b[0], b[1]);
                MMA(S[2*jp+1], aq[kk], b[2], b[3]);
            }
        }

        // ---- p = ex2(S) in fp16x2; result IS the packed A-fragment ----
        uint32_t aph[4][4];
        #pragma unroll
        for (int j = 0; j < 8; j++) {
            uint32_t u0 = h2u(__floats2half2_rn(S[j][0], S[j][1]));
            uint32_t u1 = h2u(__floats2half2_rn(S[j][2], S[j][3]));
            asm("ex2.approx.f16x2 %0, %0;" : "+r"(u0));
            asm("ex2.approx.f16x2 %0, %0;" : "+r"(u1));
            int kk = j >> 1, pc = (j & 1) * 2;
            aph[kk][pc]   = u0;
            aph[kk][pc+1] = u1;
        }

        // ---- O += P @ V ; L += P @ ones ----
        #pragma unroll
        for (int kk = 0; kk < 4; kk++) {
            MMA(L, aph[kk], ONES, ONES);
            #pragma unroll
            for (int jp = 0; jp < 4; jp++) {
                uint32_t b[4];
                LDSM4T(b, Vb + SWZ((16 * kk + brow) * 128 + 32 * jp + bcb));
                MMA(O[2*jp],   aph[kk], b[0], b[1]);
                MMA(O[2*jp+1], aph[kk], b[2], b[3]);
            }
        }

        scur = (scur == 2) ? 0 : scur + 1;
        snxt = (snxt == 2) ? 0 : snxt + 1;
    }

    // ---- finalize: L[0] = rowsum(row), L[2] = rowsum(row+8) ----
    float inv0 = 1.0f / L[0];
    float inv1 = 1.0f / L[2];

    const int row = wrow + (lane >> 2);
    const int cb  = (lane & 3) * 2;
    #pragma unroll
    for (int j = 0; j < 8; j++) {
        float2 o0 = make_float2(O[j][0] * inv0, O[j][1] * inv0);
        float2 o1 = make_float2(O[j][2] * inv1, O[j][3] * inv1);
        *reinterpret_cast<float2*>(ob + (size_t)row * D + 8 * j + cb)       = o0;
        *reinterpret_cast<float2*>(ob + (size_t)(row + 8) * D + 8 * j + cb) = o1;
    }
}

extern "C" void kernel_launch(void* const* d_in, const int* in_sizes, int n_in,
                              void* d_out, int out_size)
{
    const float* q = (const float*)d_in[0];
    const float* k = (const float*)d_in[1];
    const float* v = (const float*)d_in[2];
    float* out = (float*)d_out;
    (void)in_sizes; (void)n_in; (void)out_size;

    // fused prepass: fp32 -> fp16 for K and V
    cvt_kv<<<2 * (NELEM / 8) / 256, 256>>>(k, v);

    cudaFuncSetAttribute(attn_hmma,
                         cudaFuncAttributeMaxDynamicSharedMemorySize, SM_TOTAL);
    dim3 grid(S_LEN / BM, 32);
    attn_hmma<<<grid, 256, SM_TOTAL>>>(q, out);
}